// round 8
// baseline (speedup 1.0000x reference)
#include <cuda_runtime.h>

// Problem constants (fixed by the dataset)
#define E_N 100000
#define R_N 64
#define I_N 256
#define O_N 256

#define TILE_E 64          // entities per tile
#define N_TILES ((E_N + TILE_E - 1) / TILE_E)   // 1563
#define GRID_MAIN 296      // 2 CTAs/SM x 148 SMs, persistent

// Scratch for W_sum[r][o] = sum_i W[r][i][o]
__device__ float g_wsum[R_N * O_N];

// ---------------------------------------------------------------------------
// Kernel 1: W reduction over i.
// grid = 256: block b -> (r = b>>2, o-quarter = b&3). block = 1024 threads:
// (ic = tid>>6 in [0,16), o = tid&63). Each thread sums 16 i's, 2-stage reduce.
// ---------------------------------------------------------------------------
__global__ void __launch_bounds__(1024) wsum_kernel(const float* __restrict__ W) {
    __shared__ float red[16][64];
    const int r  = blockIdx.x >> 2;
    const int oq = blockIdx.x & 3;
    const int o  = threadIdx.x & 63;
    const int ic = threadIdx.x >> 6;          // 0..15

    const float* p = W + (size_t)r * (I_N * O_N) + (size_t)(ic * 16) * O_N
                       + oq * 64 + o;
    float acc = 0.0f;
#pragma unroll
    for (int i = 0; i < 16; ++i) acc += p[i * O_N];

    red[ic][o] = acc;
    __syncthreads();
    if (ic == 0) {
        float s = 0.0f;
#pragma unroll
        for (int k = 0; k < 16; ++k) s += red[k][o];
        g_wsum[r * O_N + oq * 64 + o] = s;
    }
}

// ---------------------------------------------------------------------------
// Kernel 2 (persistent): out[e,:] = x_sum[e] * (1/cs[e,:]) @ W_sum
// 296 CTAs x 256 threads. W_sum staged to smem ONCE per CTA, then loop tiles.
// a-tile stored duplicated ({a,a} pairs) so f32x2 FMAs need no packing movs
// and a-loads are broadcast LDS.128 covering an r-pair.
// Shared: ws 64KB + a2 32KB + xs 256B = 98560 B dynamic.
// ---------------------------------------------------------------------------
__global__ void __launch_bounds__(256, 2) rgcn_kernel(
    const float* __restrict__ x, const float* __restrict__ cs,
    float* __restrict__ out) {
    extern __shared__ float sm[];
    float* ws    = sm;                         // [64][256] floats
    float* a2    = ws + R_N * O_N;             // [64 e][64 r][2] duplicated
    float* xs_sh = a2 + TILE_E * R_N * 2;      // [64]

    const int tid  = threadIdx.x;
    const int lane = tid & 31;
    const int wid  = tid >> 5;                 // 8 warps
    const int eb   = wid * 8;                  // warp's entity group within tile
    const int tx   = lane;                     // column fragment index

    // ---- stage W_sum into shared ONCE (conflict-free float4 copy) ----
    {
        const float4* src = (const float4*)g_wsum;
        float4* dst = (float4*)ws;
#pragma unroll
        for (int k = 0; k < 16; ++k) dst[tid + k * 256] = src[tid + k * 256];
    }

    const ulonglong2* wsv = (const ulonglong2*)ws;   // row = 64 ulonglong2
    const ulonglong2* a2v = (const ulonglong2*)a2;   // e-row = 32 ulonglong2

    for (int t = blockIdx.x; t < N_TILES; t += GRID_MAIN) {
        const int e0 = t * TILE_E;

        __syncthreads();   // protect a2/xs_sh from previous tile's readers
                           // (first iter: also orders ws stores before reads)

        // ---- fill duplicated 1/cs tile: conflict-free ----
        // a2 as float4: index L in [0,2048); L holds r-pair (2p,2p+1) of
        // entity e = L>>5, p = L&31. Source = contiguous float2 of cs.
        {
            const float2* cs2 = (const float2*)cs;
            float4* adst = (float4*)a2;
#pragma unroll
            for (int k = 0; k < 8; ++k) {
                const int L = tid + k * 256;
                const int e = L >> 5;
                float2 v = make_float2(1.f, 1.f);
                if (e0 + e < E_N)
                    v = cs2[(size_t)(e0 + e) * 32 + (L & 31)];
                const float ra = 1.0f / v.x, rb = 1.0f / v.y;
                adst[L] = make_float4(ra, ra, rb, rb);
            }
        }

        // ---- x_sum: warp `wid` handles its 8 entities ----
#pragma unroll
        for (int q = 0; q < 8; ++q) {
            const int el = eb + q;
            const int e  = e0 + el;
            float s = 0.0f;
            if (e < E_N) {
                const float4* xr = (const float4*)(x + (size_t)e * I_N);
                float4 v1 = xr[lane];
                float4 v2 = xr[lane + 32];
                s = ((v1.x + v1.y) + (v1.z + v1.w)) +
                    ((v2.x + v2.y) + (v2.z + v2.w));
            }
#pragma unroll
            for (int off = 16; off > 0; off >>= 1)
                s += __shfl_xor_sync(0xffffffffu, s, off);
            if (lane == 0) xs_sh[el] = s;
        }
        __syncthreads();

        // ---- GEMM: thread = 8 entities x 8 columns, f32x2, r-pair steps ----
        unsigned long long acc[8][4];
#pragma unroll
        for (int j = 0; j < 8; ++j)
#pragma unroll
            for (int p = 0; p < 4; ++p) acc[j][p] = 0ull;

#pragma unroll 2
        for (int r = 0; r < R_N; r += 2) {
            const ulonglong2 b00 = wsv[r * 64 + tx];
            const ulonglong2 b01 = wsv[r * 64 + tx + 32];
            const ulonglong2 b10 = wsv[(r + 1) * 64 + tx];
            const ulonglong2 b11 = wsv[(r + 1) * 64 + tx + 32];
#pragma unroll
            for (int j = 0; j < 8; ++j) {
                // broadcast LDS.128: av.x = {a_r,a_r}, av.y = {a_{r+1},a_{r+1}}
                const ulonglong2 av = a2v[(eb + j) * 32 + (r >> 1)];
                asm("fma.rn.f32x2 %0, %1, %2, %0;" : "+l"(acc[j][0]) : "l"(av.x), "l"(b00.x));
                asm("fma.rn.f32x2 %0, %1, %2, %0;" : "+l"(acc[j][1]) : "l"(av.x), "l"(b00.y));
                asm("fma.rn.f32x2 %0, %1, %2, %0;" : "+l"(acc[j][2]) : "l"(av.x), "l"(b01.x));
                asm("fma.rn.f32x2 %0, %1, %2, %0;" : "+l"(acc[j][3]) : "l"(av.x), "l"(b01.y));
                asm("fma.rn.f32x2 %0, %1, %2, %0;" : "+l"(acc[j][0]) : "l"(av.y), "l"(b10.x));
                asm("fma.rn.f32x2 %0, %1, %2, %0;" : "+l"(acc[j][1]) : "l"(av.y), "l"(b10.y));
                asm("fma.rn.f32x2 %0, %1, %2, %0;" : "+l"(acc[j][2]) : "l"(av.y), "l"(b11.x));
                asm("fma.rn.f32x2 %0, %1, %2, %0;" : "+l"(acc[j][3]) : "l"(av.y), "l"(b11.y));
            }
        }

        // ---- epilogue: scale by x_sum, coalesced float4 stores ----
#pragma unroll
        for (int j = 0; j < 8; ++j) {
            const int e = e0 + eb + j;
            if (e < E_N) {
                const float s = xs_sh[eb + j];
                float2 v;
                float4 o0, o1;
                v = *(float2*)&acc[j][0]; o0.x = v.x * s; o0.y = v.y * s;
                v = *(float2*)&acc[j][1]; o0.z = v.x * s; o0.w = v.y * s;
                v = *(float2*)&acc[j][2]; o1.x = v.x * s; o1.y = v.y * s;
                v = *(float2*)&acc[j][3]; o1.z = v.x * s; o1.w = v.y * s;
                float4* orow = (float4*)(out + (size_t)e * O_N);
                orow[tx]      = o0;
                orow[tx + 32] = o1;
            }
        }
    }
}

// ---------------------------------------------------------------------------
extern "C" void kernel_launch(void* const* d_in, const int* in_sizes, int n_in,
                              void* d_out, int out_size) {
    const float* x  = (const float*)d_in[0];   // (E, I)  float32
    const float* cs = (const float*)d_in[1];   // (E, R)  float32
    const float* W  = (const float*)d_in[2];   // (R, I, O) float32
    // d_in[3] = edge_index: mathematically unused by the reference.
    float* out = (float*)d_out;                // (E, O) float32

    (void)in_sizes; (void)n_in; (void)out_size;

    const int smem_bytes =
        (R_N * O_N + TILE_E * R_N * 2 + TILE_E) * (int)sizeof(float);  // 98560
    cudaFuncSetAttribute(rgcn_kernel, cudaFuncAttributeMaxDynamicSharedMemorySize,
                         smem_bytes);

    wsum_kernel<<<256, 1024>>>(W);
    rgcn_kernel<<<GRID_MAIN, 256, smem_bytes>>>(x, cs, out);
}